// round 16
// baseline (speedup 1.0000x reference)
#include <cuda_runtime.h>
#include <cuda_fp16.h>
#include <cstdint>

#define NN 50000
#define EE 640000
#define FIN 768
#define HD 128
#define TOT (EE + NN)
#define NEG_SLOPE 0.2f

// ---------------- scratch (device globals; no allocation allowed) ----------------
__device__ __half   g_xlh[NN * HD];   // xl fp16 (consumer: aggregation)
__device__ float    g_xr[NN * HD];
__device__ __half   g_hA[NN * HD];    // layer outputs fp16
__device__ __half   g_hB[NN * HD];
__device__ __half   g_Wh[294912];     // weights fp16 n-major: per layer [256 n][K k]
__device__ int      g_counts[NN];
__device__ int      g_local[NN];
__device__ int      g_rowptr[NN + 1];
__device__ int      g_cursor[NN];
__device__ int      g_srcarr[TOT];
__device__ int      g_blocksums[64];
__device__ float    g_pool[HD];

__device__ __forceinline__ __half* bufh(int i) {
    return i == 2 ? g_hA : g_hB;
}

__device__ __forceinline__ uint32_t pack_h2(float a, float b) {
    __half2 h = __floats2half2_rn(a, b);
    return *reinterpret_cast<uint32_t*>(&h);
}

__device__ __forceinline__ void cpa16(uint32_t dst, const void* src) {
    asm volatile("cp.async.cg.shared.global [%0], [%1], 16;" :: "r"(dst), "l"(src) : "memory");
}
__device__ __forceinline__ void cpa8z(uint32_t dst, const void* src, int srcsize) {
    asm volatile("cp.async.ca.shared.global [%0], [%1], 8, %2;"
                 :: "r"(dst), "l"(src), "r"(srcsize) : "memory");
}
__device__ __forceinline__ void cpa_commit() {
    asm volatile("cp.async.commit_group;" ::: "memory");
}
__device__ __forceinline__ void cpa_wait0() {
    asm volatile("cp.async.wait_group 0;" ::: "memory");
}

// ---------------- CSR build ----------------
__global__ void k_init() {
    int i = blockIdx.x * blockDim.x + threadIdx.x;
    if (i < NN) g_counts[i] = 1;          // self loop
    if (i < HD) g_pool[i] = 0.f;
}

__global__ void k_hist(const int* __restrict__ ei) {
    int e = blockIdx.x * blockDim.x + threadIdx.x;
    if (e < EE) atomicAdd(&g_counts[ei[EE + e]], 1);
}

__global__ void k_scan_block() {
    __shared__ int sm[1024];
    int i = blockIdx.x * 1024 + threadIdx.x;
    int v = (i < NN) ? g_counts[i] : 0;
    sm[threadIdx.x] = v;
    __syncthreads();
    for (int off = 1; off < 1024; off <<= 1) {
        int t = (threadIdx.x >= off) ? sm[threadIdx.x - off] : 0;
        __syncthreads();
        sm[threadIdx.x] += t;
        __syncthreads();
    }
    if (i < NN) g_local[i] = sm[threadIdx.x] - v;   // exclusive
    if (threadIdx.x == 1023) g_blocksums[blockIdx.x] = sm[1023];
}

__global__ void k_scan_top(int nb) {
    __shared__ int sm[64];
    int t = threadIdx.x;
    int v = (t < nb) ? g_blocksums[t] : 0;
    sm[t] = v;
    __syncthreads();
    for (int off = 1; off < 64; off <<= 1) {
        int u = (t >= off) ? sm[t - off] : 0;
        __syncthreads();
        sm[t] += u;
        __syncthreads();
    }
    if (t < nb) g_blocksums[t] = sm[t] - v;         // exclusive
}

__global__ void k_finalize_csr() {
    int i = blockIdx.x * blockDim.x + threadIdx.x;
    if (i < NN) {
        int off = g_local[i] + g_blocksums[i >> 10];
        g_rowptr[i] = off;
        g_cursor[i] = off + 1;      // slot 0 reserved for self loop
        g_srcarr[off] = i;          // self loop
    }
    if (i == 0) g_rowptr[NN] = TOT;
}

__global__ void k_scatter(const int* __restrict__ ei) {
    int e = blockIdx.x * blockDim.x + threadIdx.x;
    if (e < EE) {
        int s = ei[e];
        int d = ei[EE + e];
        g_srcarr[atomicAdd(&g_cursor[d], 1)] = s;
    }
}

// ---------------- weight conversion: fp32 [K,128]x2 -> fp16 n-major [256][K] per layer -------
__global__ void k_wconv(const float* w1l, const float* w1r, const float* w2l, const float* w2r,
                        const float* w3l, const float* w3r, const float* w4l, const float* w4r) {
    int idx = blockIdx.x * blockDim.x + threadIdx.x;   // 294912 threads
    int K, base;
    const float *Wl, *Wr;
    if      (idx < 196608) { base = 0;      K = FIN; Wl = w1l; Wr = w1r; }
    else if (idx < 229376) { base = 196608; K = HD;  Wl = w2l; Wr = w2r; }
    else if (idx < 262144) { base = 229376; K = HD;  Wl = w3l; Wr = w3r; }
    else                   { base = 262144; K = HD;  Wl = w4l; Wr = w4r; }
    int local = idx - base;
    int n = local / K;
    int k = local - n * K;
    const float* W = (n < 128) ? Wl : Wr;
    g_Wh[idx] = __float2half_rn(W[k * 128 + (n & 127)]);
}

// ---------------- fp16 dual GEMM: tile M=64, N=256, ldmatrix + cp.async ----------------
#define ASTRH 40    // halfs per smem row (20 banks -> ldmatrix conflict-free)
#define KCH 32
#define SM_A(b) ((b) * 2560)
#define SM_B(b) (5120 + (b) * 10240)
#define GM_SMEM_BYTES 51200

#define LDSM4(r0, r1, r2, r3, addr) \
    asm volatile("ldmatrix.sync.aligned.m8n8.x4.shared.b16 {%0,%1,%2,%3}, [%4];" \
        : "=r"(r0), "=r"(r1), "=r"(r2), "=r"(r3) : "r"(addr))

template<int ASRC>
__global__ void __launch_bounds__(256, 2)
k_gemm_dual(const float* __restrict__ Aext, int Asel, int wbase, int M, int K) {
    extern __shared__ __half smh[];
    const float*  __restrict__ Af = Aext;
    const __half* __restrict__ Ah = (ASRC == 1) ? bufh(Asel) : nullptr;
    const __half* __restrict__ Bsrc = g_Wh + wbase;

    const int tid  = threadIdx.x;
    const int wid  = tid >> 5;
    const int lane = tid & 31;
    const int g = lane >> 2;
    const int t = lane & 3;
    const int warpM = wid & 1;   // 2 warps in M (32 rows each)
    const int warpN = wid >> 1;  // 4 warps in N (64 cols each)
    const int row0 = blockIdx.x * 64;

    const uint32_t smbase = (uint32_t)__cvta_generic_to_shared(smh);

    // ldmatrix lane-derived offsets
    const int lr  = lane & 7;
    const int lmi = lane >> 3;                 // 0..3
    const int a_row_off = lr + (lmi & 1) * 8;
    const int a_k_off   = (lmi >> 1) * 8;
    const int b_n_off   = (lmi >> 1) * 8 + lr;
    const int b_k_off   = (lmi & 1) * 8;

    float acc[2][8][4];
    #pragma unroll
    for (int i = 0; i < 2; i++)
        #pragma unroll
        for (int j = 0; j < 8; j++)
            #pragma unroll
            for (int k = 0; k < 4; k++) acc[i][j][k] = 0.f;

    // A staging indices (per thread, 2 slots)
    const int ar0 = tid >> 3, aq0 = tid & 7;
    const int ar1 = (tid + 256) >> 3, aq1 = (tid + 256) & 7;
    const int gr0 = row0 + ar0, gr1 = row0 + ar1;
    float4 raf[2];   // layer-1 fp32 staging only

    auto loadA_reg = [&](int k0) {   // ASRC == 0
        raf[0] = (gr0 < M) ? *reinterpret_cast<const float4*>(&Af[(size_t)gr0 * K + k0 + aq0 * 4])
                           : make_float4(0.f, 0.f, 0.f, 0.f);
        raf[1] = (gr1 < M) ? *reinterpret_cast<const float4*>(&Af[(size_t)gr1 * K + k0 + aq1 * 4])
                           : make_float4(0.f, 0.f, 0.f, 0.f);
    };
    auto storeA_reg = [&](int bi) {  // ASRC == 0
        uint2 h0, h1;
        h0.x = pack_h2(raf[0].x, raf[0].y); h0.y = pack_h2(raf[0].z, raf[0].w);
        h1.x = pack_h2(raf[1].x, raf[1].y); h1.y = pack_h2(raf[1].z, raf[1].w);
        *reinterpret_cast<uint2*>(&smh[SM_A(bi) + ar0 * ASTRH + aq0 * 4]) = h0;
        *reinterpret_cast<uint2*>(&smh[SM_A(bi) + ar1 * ASTRH + aq1 * 4]) = h1;
    };
    auto loadA_async = [&](int k0, int bi) {   // ASRC == 1
        cpa8z(smbase + 2u * (SM_A(bi) + ar0 * ASTRH + aq0 * 4),
              &Ah[(size_t)gr0 * K + k0 + aq0 * 4], (gr0 < M) ? 8 : 0);
        cpa8z(smbase + 2u * (SM_A(bi) + ar1 * ASTRH + aq1 * 4),
              &Ah[(size_t)gr1 * K + k0 + aq1 * 4], (gr1 < M) ? 8 : 0);
    };
    auto loadB_async = [&](int k0, int bi) {
        #pragma unroll
        for (int i = 0; i < 4; i++) {
            int s = tid + i * 256;
            int n = s >> 2, kq = s & 3;
            cpa16(smbase + 2u * (SM_B(bi) + n * ASTRH + kq * 8),
                  &Bsrc[(size_t)n * K + k0 + kq * 8]);
        }
    };

    // ---- chunk 0 ----
    if (ASRC == 0) loadA_reg(0); else loadA_async(0, 0);
    loadB_async(0, 0);
    cpa_commit();
    if (ASRC == 0) storeA_reg(0);
    cpa_wait0();
    __syncthreads();

    const int niter = K / KCH;
    int cur = 0;
    for (int it = 0; it < niter; it++) {
        const bool has_next = (it + 1 < niter);
        if (has_next) {
            const int k0n = (it + 1) * KCH;
            const int nxt = cur ^ 1;
            if (ASRC == 0) loadA_reg(k0n); else loadA_async(k0n, nxt);
            loadB_async(k0n, nxt);
            cpa_commit();
        }

        const uint32_t saA = smbase + 2u * SM_A(cur);
        const uint32_t saB = smbase + 2u * SM_B(cur);
        #pragma unroll
        for (int ks = 0; ks < 2; ks++) {
            uint32_t af[2][4];
            #pragma unroll
            for (int mt = 0; mt < 2; mt++) {
                uint32_t addr = saA + 2u * ((warpM * 32 + mt * 16 + a_row_off) * ASTRH
                                            + a_k_off + ks * 16);
                LDSM4(af[mt][0], af[mt][1], af[mt][2], af[mt][3], addr);
            }
            uint32_t bf[8][2];
            #pragma unroll
            for (int p = 0; p < 4; p++) {
                uint32_t addr = saB + 2u * ((warpN * 64 + p * 16 + b_n_off) * ASTRH
                                            + b_k_off + ks * 16);
                LDSM4(bf[2 * p][0], bf[2 * p][1], bf[2 * p + 1][0], bf[2 * p + 1][1], addr);
            }
            #pragma unroll
            for (int mt = 0; mt < 2; mt++)
                #pragma unroll
                for (int nt = 0; nt < 8; nt++) {
                    asm volatile(
                        "mma.sync.aligned.m16n8k16.row.col.f32.f16.f16.f32 "
                        "{%0,%1,%2,%3}, {%4,%5,%6,%7}, {%8,%9}, {%0,%1,%2,%3};"
                        : "+f"(acc[mt][nt][0]), "+f"(acc[mt][nt][1]),
                          "+f"(acc[mt][nt][2]), "+f"(acc[mt][nt][3])
                        : "r"(af[mt][0]), "r"(af[mt][1]), "r"(af[mt][2]), "r"(af[mt][3]),
                          "r"(bf[nt][0]), "r"(bf[nt][1]));
                }
        }

        if (has_next) {
            if (ASRC == 0) storeA_reg(cur ^ 1);
            cpa_wait0();
        }
        __syncthreads();
        cur ^= 1;
    }

    // epilogue: warpN 0,1 -> g_xlh (fp16); warpN 2,3 -> g_xr (fp32)
    #pragma unroll
    for (int mt = 0; mt < 2; mt++) {
        int r0 = row0 + warpM * 32 + mt * 16 + g;
        #pragma unroll
        for (int nt = 0; nt < 8; nt++) {
            int c = warpN * 64 + nt * 8 + t * 2;
            if (c < 128) {
                if (r0 < M)
                    *reinterpret_cast<uint32_t*>(&g_xlh[(size_t)r0 * 128 + c]) =
                        pack_h2(acc[mt][nt][0], acc[mt][nt][1]);
                if (r0 + 8 < M)
                    *reinterpret_cast<uint32_t*>(&g_xlh[(size_t)(r0 + 8) * 128 + c]) =
                        pack_h2(acc[mt][nt][2], acc[mt][nt][3]);
            } else {
                int cc = c - 128;
                if (r0 < M)
                    *reinterpret_cast<float2*>(&g_xr[(size_t)r0 * 128 + cc]) =
                        make_float2(acc[mt][nt][0], acc[mt][nt][1]);
                if (r0 + 8 < M)
                    *reinterpret_cast<float2*>(&g_xr[(size_t)(r0 + 8) * 128 + cc]) =
                        make_float2(acc[mt][nt][2], acc[mt][nt][3]);
            }
        }
    }
}

// ---------------- GATv2 aggregation: warp/node, dual softmax states, fp16 in/out ----------------
__device__ __forceinline__ float lrelu(float v) { return v > 0.f ? v : NEG_SLOPE * v; }

__device__ __forceinline__ void osm_update(float& m, float& s, float4& acc,
                                           float eh, const float4& xlv) {
    if (eh > m) {
        float sc = __expf(m - eh);
        s *= sc;
        acc.x *= sc; acc.y *= sc; acc.z *= sc; acc.w *= sc;
        m = eh;
    }
    float w = __expf(eh - m);
    s += w;
    acc.x += w * xlv.x; acc.y += w * xlv.y;
    acc.z += w * xlv.z; acc.w += w * xlv.w;
}

__device__ __forceinline__ float4 load_xl_h(const __half* xlh, int node, int lane) {
    const uint2 raw = *reinterpret_cast<const uint2*>(&xlh[(size_t)node * HD + lane * 4]);
    float2 f0 = __half22float2(*reinterpret_cast<const __half2*>(&raw.x));
    float2 f1 = __half22float2(*reinterpret_cast<const __half2*>(&raw.y));
    return make_float4(f0.x, f0.y, f1.x, f1.y);
}

__global__ void k_aggregate(const float* __restrict__ att, const float* __restrict__ bias,
                            int outsel, int do_relu) {
    int warp = (blockIdx.x * blockDim.x + threadIdx.x) >> 5;
    if (warp >= NN) return;
    int lane = threadIdx.x & 31;
    const __half* __restrict__ xlh = g_xlh;
    __half* __restrict__ out = bufh(outsel);

    const float4 xrv  = *reinterpret_cast<const float4*>(&g_xr[(size_t)warp * HD + lane * 4]);
    const float4 attv = *reinterpret_cast<const float4*>(&att[lane * 4]);

    float m0 = -1e30f, s0 = 0.f, m1 = -1e30f, s1 = 0.f;
    float4 a0 = make_float4(0.f, 0.f, 0.f, 0.f);
    float4 a1 = make_float4(0.f, 0.f, 0.f, 0.f);

    const int beg = g_rowptr[warp];
    const int end = g_rowptr[warp + 1];

    int e = beg;
    for (; e + 1 < end; e += 2) {
        int sA = g_srcarr[e];
        int sB = g_srcarr[e + 1];
        const float4 xA = load_xl_h(xlh, sA, lane);
        const float4 xB = load_xl_h(xlh, sB, lane);

        float pA = lrelu(xA.x + xrv.x) * attv.x + lrelu(xA.y + xrv.y) * attv.y
                 + lrelu(xA.z + xrv.z) * attv.z + lrelu(xA.w + xrv.w) * attv.w;
        float pB = lrelu(xB.x + xrv.x) * attv.x + lrelu(xB.y + xrv.y) * attv.y
                 + lrelu(xB.z + xrv.z) * attv.z + lrelu(xB.w + xrv.w) * attv.w;
        pA += __shfl_xor_sync(0xffffffffu, pA, 1);
        pB += __shfl_xor_sync(0xffffffffu, pB, 1);
        pA += __shfl_xor_sync(0xffffffffu, pA, 2);
        pB += __shfl_xor_sync(0xffffffffu, pB, 2);
        pA += __shfl_xor_sync(0xffffffffu, pA, 4);
        pB += __shfl_xor_sync(0xffffffffu, pB, 4);

        osm_update(m0, s0, a0, pA, xA);
        osm_update(m1, s1, a1, pB, xB);
    }
    if (e < end) {
        int sA = g_srcarr[e];
        const float4 xA = load_xl_h(xlh, sA, lane);
        float pA = lrelu(xA.x + xrv.x) * attv.x + lrelu(xA.y + xrv.y) * attv.y
                 + lrelu(xA.z + xrv.z) * attv.z + lrelu(xA.w + xrv.w) * attv.w;
        pA += __shfl_xor_sync(0xffffffffu, pA, 1);
        pA += __shfl_xor_sync(0xffffffffu, pA, 2);
        pA += __shfl_xor_sync(0xffffffffu, pA, 4);
        osm_update(m0, s0, a0, pA, xA);
    }

    // merge the two states (exact)
    float m = fmaxf(m0, m1);
    float c0 = __expf(m0 - m);
    float c1 = (s1 > 0.f) ? __expf(m1 - m) : 0.f;
    float s = s0 * c0 + s1 * c1;
    float4 acc;
    acc.x = a0.x * c0 + a1.x * c1;
    acc.y = a0.y * c0 + a1.y * c1;
    acc.z = a0.z * c0 + a1.z * c1;
    acc.w = a0.w * c0 + a1.w * c1;

    float inv = 1.f / (s + 1e-16f);
    const float4 bv = *reinterpret_cast<const float4*>(&bias[lane * 4]);
    float4 o;
    o.x = acc.x * inv + bv.x;
    o.y = acc.y * inv + bv.y;
    o.z = acc.z * inv + bv.z;
    o.w = acc.w * inv + bv.w;
    if (do_relu) {
        o.x = fmaxf(o.x, 0.f); o.y = fmaxf(o.y, 0.f);
        o.z = fmaxf(o.z, 0.f); o.w = fmaxf(o.w, 0.f);
    }
    uint2 ov;
    ov.x = pack_h2(o.x, o.y);
    ov.y = pack_h2(o.z, o.w);
    *reinterpret_cast<uint2*>(&out[(size_t)warp * HD + lane * 4]) = ov;
}

// ---------------- pooling + classifier ----------------
__global__ void k_pool(int hsel) {
    const __half* __restrict__ h = bufh(hsel);
    int col = threadIdx.x;   // blockDim = 128
    float acc = 0.f;
    for (int r = blockIdx.x; r < NN; r += gridDim.x)
        acc += __half2float(h[(size_t)r * HD + col]);
    atomicAdd(&g_pool[col], acc);
}

__global__ void k_classify(const float* __restrict__ W, const float* __restrict__ b,
                           float* __restrict__ out) {
    int j = threadIdx.x;
    if (j < 2) {
        float s = 0.f;
        const float invn = 1.f / (float)NN;
        for (int k = 0; k < HD; k++)
            s += g_pool[k] * invn * W[k * 2 + j];
        out[j] = s + b[j];
    }
}

// ---------------- launch ----------------
extern "C" void kernel_launch(void* const* d_in, const int* in_sizes, int n_in,
                              void* d_out, int out_size) {
    const float* x  = (const float*)d_in[0];
    const int*   ei = (const int*)d_in[1];   // int32 (JAX x64 disabled)
    const float* Wl[4]  = {(const float*)d_in[2],  (const float*)d_in[6],
                           (const float*)d_in[10], (const float*)d_in[14]};
    const float* Wr[4]  = {(const float*)d_in[3],  (const float*)d_in[7],
                           (const float*)d_in[11], (const float*)d_in[15]};
    const float* att[4] = {(const float*)d_in[4],  (const float*)d_in[8],
                           (const float*)d_in[12], (const float*)d_in[16]};
    const float* bia[4] = {(const float*)d_in[5],  (const float*)d_in[9],
                           (const float*)d_in[13], (const float*)d_in[17]};
    const float* clfW = (const float*)d_in[18];
    const float* clfb = (const float*)d_in[19];
    float* out = (float*)d_out;

    cudaFuncSetAttribute(k_gemm_dual<0>, cudaFuncAttributeMaxDynamicSharedMemorySize,
                         GM_SMEM_BYTES);
    cudaFuncSetAttribute(k_gemm_dual<1>, cudaFuncAttributeMaxDynamicSharedMemorySize,
                         GM_SMEM_BYTES);

    const int TB = 256;
    const int gN  = (NN + TB - 1) / TB;
    const int gE  = (EE + TB - 1) / TB;
    const int gSc = (NN + 1023) / 1024;            // 49
    const int gGm = (NN + 63) / 64;                // 782 (M=64 dual-output tiles)
    const int gAg = (NN * 32 + TB - 1) / TB;       // warp per node

    // CSR build + weight conversion; layer-1 GEMM placed 4th (ncu capture window)
    k_init<<<gN, TB>>>();
    k_hist<<<gE, TB>>>(ei);
    k_wconv<<<294912 / TB, TB>>>(Wl[0], Wr[0], Wl[1], Wr[1], Wl[2], Wr[2], Wl[3], Wr[3]);
    k_gemm_dual<0><<<gGm, TB, GM_SMEM_BYTES>>>(x, -1, 0, NN, FIN);   // layer 1 GEMM
    k_scan_block<<<gSc, 1024>>>();
    k_scan_top<<<1, 64>>>(gSc);
    k_finalize_csr<<<gN, TB>>>();
    k_scatter<<<gE, TB>>>(ei);

    // layer 1 aggregation
    k_aggregate<<<gAg, TB>>>(att[0], bia[0], 2, 1);
    // layer 2: A = hA(2)
    k_gemm_dual<1><<<gGm, TB, GM_SMEM_BYTES>>>(nullptr, 2, 196608, NN, HD);
    k_aggregate<<<gAg, TB>>>(att[1], bia[1], 3, 1);
    // layer 3: A = hB(3)
    k_gemm_dual<1><<<gGm, TB, GM_SMEM_BYTES>>>(nullptr, 3, 229376, NN, HD);
    k_aggregate<<<gAg, TB>>>(att[2], bia[2], 2, 1);
    // layer 4 (no relu): A = hA(2)
    k_gemm_dual<1><<<gGm, TB, GM_SMEM_BYTES>>>(nullptr, 2, 262144, NN, HD);
    k_aggregate<<<gAg, TB>>>(att[3], bia[3], 3, 0);

    // mean-pool + classifier
    k_pool<<<512, 128>>>(3);
    k_classify<<<1, 32>>>(clfW, clfb, out);
}

// round 17
// speedup vs baseline: 1.0126x; 1.0126x over previous
#include <cuda_runtime.h>
#include <cuda_fp16.h>
#include <cstdint>

#define NN 50000
#define EE 640000
#define FIN 768
#define HD 128
#define TOT (EE + NN)
#define NEG_SLOPE 0.2f

// ---------------- scratch (device globals; no allocation allowed) ----------------
__device__ __half   g_xlh[NN * HD];   // xl fp16 (consumer: aggregation)
__device__ float    g_xr[NN * HD];
__device__ __half   g_hA[NN * HD];    // layer outputs fp16
__device__ __half   g_hB[NN * HD];
__device__ __half   g_Wh[294912];     // weights fp16 n-major: per layer [256 n][K k]
__device__ int      g_counts[NN];
__device__ int      g_local[NN];
__device__ int      g_rowptr[NN + 1];
__device__ int      g_cursor[NN];
__device__ int      g_srcarr[TOT];
__device__ int      g_blocksums[64];
__device__ float    g_pool[HD];

__device__ __forceinline__ __half* bufh(int i) {
    return i == 2 ? g_hA : g_hB;
}

__device__ __forceinline__ uint32_t pack_h2(float a, float b) {
    __half2 h = __floats2half2_rn(a, b);
    return *reinterpret_cast<uint32_t*>(&h);
}

__device__ __forceinline__ void cpa16(uint32_t dst, const void* src) {
    asm volatile("cp.async.cg.shared.global [%0], [%1], 16;" :: "r"(dst), "l"(src) : "memory");
}
__device__ __forceinline__ void cpa16z(uint32_t dst, const void* src, int srcsize) {
    asm volatile("cp.async.cg.shared.global [%0], [%1], 16, %2;"
                 :: "r"(dst), "l"(src), "r"(srcsize) : "memory");
}
__device__ __forceinline__ void cpa_commit() {
    asm volatile("cp.async.commit_group;" ::: "memory");
}
__device__ __forceinline__ void cpa_wait0() {
    asm volatile("cp.async.wait_group 0;" ::: "memory");
}
__device__ __forceinline__ void cpa_wait1() {
    asm volatile("cp.async.wait_group 1;" ::: "memory");
}

// ---------------- CSR build ----------------
__global__ void k_init() {
    int i = blockIdx.x * blockDim.x + threadIdx.x;
    if (i < NN) g_counts[i] = 1;          // self loop
    if (i < HD) g_pool[i] = 0.f;
}

__global__ void k_hist(const int* __restrict__ ei) {
    int e = blockIdx.x * blockDim.x + threadIdx.x;
    if (e < EE) atomicAdd(&g_counts[ei[EE + e]], 1);
}

__global__ void k_scan_block() {
    __shared__ int sm[1024];
    int i = blockIdx.x * 1024 + threadIdx.x;
    int v = (i < NN) ? g_counts[i] : 0;
    sm[threadIdx.x] = v;
    __syncthreads();
    for (int off = 1; off < 1024; off <<= 1) {
        int t = (threadIdx.x >= off) ? sm[threadIdx.x - off] : 0;
        __syncthreads();
        sm[threadIdx.x] += t;
        __syncthreads();
    }
    if (i < NN) g_local[i] = sm[threadIdx.x] - v;   // exclusive
    if (threadIdx.x == 1023) g_blocksums[blockIdx.x] = sm[1023];
}

__global__ void k_scan_top(int nb) {
    __shared__ int sm[64];
    int t = threadIdx.x;
    int v = (t < nb) ? g_blocksums[t] : 0;
    sm[t] = v;
    __syncthreads();
    for (int off = 1; off < 64; off <<= 1) {
        int u = (t >= off) ? sm[t - off] : 0;
        __syncthreads();
        sm[t] += u;
        __syncthreads();
    }
    if (t < nb) g_blocksums[t] = sm[t] - v;         // exclusive
}

__global__ void k_finalize_csr() {
    int i = blockIdx.x * blockDim.x + threadIdx.x;
    if (i < NN) {
        int off = g_local[i] + g_blocksums[i >> 10];
        g_rowptr[i] = off;
        g_cursor[i] = off + 1;      // slot 0 reserved for self loop
        g_srcarr[off] = i;          // self loop
    }
    if (i == 0) g_rowptr[NN] = TOT;
}

__global__ void k_scatter(const int* __restrict__ ei) {
    int e = blockIdx.x * blockDim.x + threadIdx.x;
    if (e < EE) {
        int s = ei[e];
        int d = ei[EE + e];
        g_srcarr[atomicAdd(&g_cursor[d], 1)] = s;
    }
}

// ---------------- weight conversion: fp32 [K,128]x2 -> fp16 n-major [256][K] per layer -------
__global__ void k_wconv(const float* w1l, const float* w1r, const float* w2l, const float* w2r,
                        const float* w3l, const float* w3r, const float* w4l, const float* w4r) {
    int idx = blockIdx.x * blockDim.x + threadIdx.x;   // 294912 threads
    int K, base;
    const float *Wl, *Wr;
    if      (idx < 196608) { base = 0;      K = FIN; Wl = w1l; Wr = w1r; }
    else if (idx < 229376) { base = 196608; K = HD;  Wl = w2l; Wr = w2r; }
    else if (idx < 262144) { base = 229376; K = HD;  Wl = w3l; Wr = w3r; }
    else                   { base = 262144; K = HD;  Wl = w4l; Wr = w4r; }
    int local = idx - base;
    int n = local / K;
    int k = local - n * K;
    const float* W = (n < 128) ? Wl : Wr;
    g_Wh[idx] = __float2half_rn(W[k * 128 + (n & 127)]);
}

// ---------------- fp16 dual GEMM: tile M=64, N=256, ldmatrix + 3-stage cp.async -----------
#define ASTRH 40    // halfs per smem row (20 banks -> ldmatrix conflict-free)
#define KCH 32
// stage s: A at s*12800, B at s*12800+2560 (halfs); 3 stages
#define SM_A(s) ((s) * 12800)
#define SM_B(s) ((s) * 12800 + 2560)
#define GM_SMEM_BYTES 76800

#define LDSM4(r0, r1, r2, r3, addr) \
    asm volatile("ldmatrix.sync.aligned.m8n8.x4.shared.b16 {%0,%1,%2,%3}, [%4];" \
        : "=r"(r0), "=r"(r1), "=r"(r2), "=r"(r3) : "r"(addr))

template<int ASRC>
__global__ void __launch_bounds__(256, 2)
k_gemm_dual(const float* __restrict__ Aext, int Asel, int wbase, int M, int K) {
    extern __shared__ __half smh[];
    const float*  __restrict__ Af = Aext;
    const __half* __restrict__ Ah = (ASRC == 1) ? bufh(Asel) : nullptr;
    const __half* __restrict__ Bsrc = g_Wh + wbase;

    const int tid  = threadIdx.x;
    const int wid  = tid >> 5;
    const int lane = tid & 31;
    const int g = lane >> 2;
    const int t = lane & 3;
    const int warpM = wid & 1;   // 2 warps in M (32 rows each)
    const int warpN = wid >> 1;  // 4 warps in N (64 cols each)
    const int row0 = blockIdx.x * 64;

    const uint32_t smbase = (uint32_t)__cvta_generic_to_shared(smh);

    // ldmatrix lane-derived offsets
    const int lr  = lane & 7;
    const int lmi = lane >> 3;                 // 0..3
    const int a_row_off = lr + (lmi & 1) * 8;
    const int a_k_off   = (lmi >> 1) * 8;
    const int b_n_off   = (lmi >> 1) * 8 + lr;
    const int b_k_off   = (lmi & 1) * 8;

    float acc[2][8][4];
    #pragma unroll
    for (int i = 0; i < 2; i++)
        #pragma unroll
        for (int j = 0; j < 8; j++)
            #pragma unroll
            for (int k = 0; k < 4; k++) acc[i][j][k] = 0.f;

    // A staging indices
    // fp32 path: 2 float4 slots/thread
    const int ar0 = tid >> 3, aq0 = tid & 7;
    const int ar1 = (tid + 256) >> 3, aq1 = (tid + 256) & 7;
    const int gr0 = row0 + ar0, gr1 = row0 + ar1;
    // fp16 path: 1 x 16B slot/thread
    const int ahr = tid >> 2, ahq = (tid & 3) * 8;
    const int grh = row0 + ahr;
    float4 raf[2];

    auto loadA_reg = [&](int k0) {   // ASRC == 0
        raf[0] = (gr0 < M) ? *reinterpret_cast<const float4*>(&Af[(size_t)gr0 * K + k0 + aq0 * 4])
                           : make_float4(0.f, 0.f, 0.f, 0.f);
        raf[1] = (gr1 < M) ? *reinterpret_cast<const float4*>(&Af[(size_t)gr1 * K + k0 + aq1 * 4])
                           : make_float4(0.f, 0.f, 0.f, 0.f);
    };
    auto storeA_reg = [&](int st) {  // ASRC == 0
        uint2 h0, h1;
        h0.x = pack_h2(raf[0].x, raf[0].y); h0.y = pack_h2(raf[0].z, raf[0].w);
        h1.x = pack_h2(raf[1].x, raf[1].y); h1.y = pack_h2(raf[1].z, raf[1].w);
        *reinterpret_cast<uint2*>(&smh[SM_A(st) + ar0 * ASTRH + aq0 * 4]) = h0;
        *reinterpret_cast<uint2*>(&smh[SM_A(st) + ar1 * ASTRH + aq1 * 4]) = h1;
    };
    auto loadA_async = [&](int k0, int st) {   // ASRC == 1
        cpa16z(smbase + 2u * (SM_A(st) + ahr * ASTRH + ahq),
               &Ah[(size_t)grh * K + k0 + ahq], (grh < M) ? 16 : 0);
    };
    auto loadB_async = [&](int k0, int st) {
        #pragma unroll
        for (int i = 0; i < 4; i++) {
            int s = tid + i * 256;
            int n = s >> 2, kq = s & 3;
            cpa16(smbase + 2u * (SM_B(st) + n * ASTRH + kq * 8),
                  &Bsrc[(size_t)n * K + k0 + kq * 8]);
        }
    };

    const int niter = K / KCH;

    // ---- prologue: stages for chunks 0 and 1 ----
    if (ASRC == 1) loadA_async(0, 0);
    loadB_async(0, 0);
    cpa_commit();
    if (niter > 1) {
        if (ASRC == 1) loadA_async(KCH, 1);
        loadB_async(KCH, 1);
        cpa_commit();
    }
    if (ASRC == 0) {
        loadA_reg(0); storeA_reg(0);
        if (niter > 1) loadA_reg(KCH);   // chunk 1 in regs
    }
    if (niter > 1) cpa_wait1(); else cpa_wait0();
    __syncthreads();

    for (int it = 0; it < niter; it++) {
        // issue stage for chunk it+2
        if (it + 2 < niter) {
            const int st2 = (it + 2) % 3;
            if (ASRC == 1) loadA_async((it + 2) * KCH, st2);
            loadB_async((it + 2) * KCH, st2);
            cpa_commit();
        }
        if (ASRC == 0) {
            if (it + 1 < niter) storeA_reg((it + 1) % 3);   // regs -> smem for chunk it+1
            if (it + 2 < niter) loadA_reg((it + 2) * KCH);  // LDG chunk it+2
        }

        const int cst = it % 3;
        const uint32_t saA = smbase + 2u * SM_A(cst);
        const uint32_t saB = smbase + 2u * SM_B(cst);
        #pragma unroll
        for (int ks = 0; ks < 2; ks++) {
            uint32_t af[2][4];
            #pragma unroll
            for (int mt = 0; mt < 2; mt++) {
                uint32_t addr = saA + 2u * ((warpM * 32 + mt * 16 + a_row_off) * ASTRH
                                            + a_k_off + ks * 16);
                LDSM4(af[mt][0], af[mt][1], af[mt][2], af[mt][3], addr);
            }
            uint32_t bf[8][2];
            #pragma unroll
            for (int p = 0; p < 4; p++) {
                uint32_t addr = saB + 2u * ((warpN * 64 + p * 16 + b_n_off) * ASTRH
                                            + b_k_off + ks * 16);
                LDSM4(bf[2 * p][0], bf[2 * p][1], bf[2 * p + 1][0], bf[2 * p + 1][1], addr);
            }
            #pragma unroll
            for (int mt = 0; mt < 2; mt++)
                #pragma unroll
                for (int nt = 0; nt < 8; nt++) {
                    asm volatile(
                        "mma.sync.aligned.m16n8k16.row.col.f32.f16.f16.f32 "
                        "{%0,%1,%2,%3}, {%4,%5,%6,%7}, {%8,%9}, {%0,%1,%2,%3};"
                        : "+f"(acc[mt][nt][0]), "+f"(acc[mt][nt][1]),
                          "+f"(acc[mt][nt][2]), "+f"(acc[mt][nt][3])
                        : "r"(af[mt][0]), "r"(af[mt][1]), "r"(af[mt][2]), "r"(af[mt][3]),
                          "r"(bf[nt][0]), "r"(bf[nt][1]));
                }
        }

        // wait until chunk it+1's group is complete
        if (it + 1 < niter) {
            if (it + 2 < niter) cpa_wait1(); else cpa_wait0();
        }
        __syncthreads();
    }

    // epilogue: warpN 0,1 -> g_xlh (fp16); warpN 2,3 -> g_xr (fp32)
    #pragma unroll
    for (int mt = 0; mt < 2; mt++) {
        int r0 = row0 + warpM * 32 + mt * 16 + g;
        #pragma unroll
        for (int nt = 0; nt < 8; nt++) {
            int c = warpN * 64 + nt * 8 + t * 2;
            if (c < 128) {
                if (r0 < M)
                    *reinterpret_cast<uint32_t*>(&g_xlh[(size_t)r0 * 128 + c]) =
                        pack_h2(acc[mt][nt][0], acc[mt][nt][1]);
                if (r0 + 8 < M)
                    *reinterpret_cast<uint32_t*>(&g_xlh[(size_t)(r0 + 8) * 128 + c]) =
                        pack_h2(acc[mt][nt][2], acc[mt][nt][3]);
            } else {
                int cc = c - 128;
                if (r0 < M)
                    *reinterpret_cast<float2*>(&g_xr[(size_t)r0 * 128 + cc]) =
                        make_float2(acc[mt][nt][0], acc[mt][nt][1]);
                if (r0 + 8 < M)
                    *reinterpret_cast<float2*>(&g_xr[(size_t)(r0 + 8) * 128 + cc]) =
                        make_float2(acc[mt][nt][2], acc[mt][nt][3]);
            }
        }
    }
}

// ---------------- GATv2 aggregation: warp/node, dual softmax states, fp16 in/out ----------------
__device__ __forceinline__ float lrelu(float v) { return v > 0.f ? v : NEG_SLOPE * v; }

__device__ __forceinline__ void osm_update(float& m, float& s, float4& acc,
                                           float eh, const float4& xlv) {
    if (eh > m) {
        float sc = __expf(m - eh);
        s *= sc;
        acc.x *= sc; acc.y *= sc; acc.z *= sc; acc.w *= sc;
        m = eh;
    }
    float w = __expf(eh - m);
    s += w;
    acc.x += w * xlv.x; acc.y += w * xlv.y;
    acc.z += w * xlv.z; acc.w += w * xlv.w;
}

__device__ __forceinline__ float4 load_xl_h(const __half* xlh, int node, int lane) {
    const uint2 raw = *reinterpret_cast<const uint2*>(&xlh[(size_t)node * HD + lane * 4]);
    float2 f0 = __half22float2(*reinterpret_cast<const __half2*>(&raw.x));
    float2 f1 = __half22float2(*reinterpret_cast<const __half2*>(&raw.y));
    return make_float4(f0.x, f0.y, f1.x, f1.y);
}

__global__ void k_aggregate(const float* __restrict__ att, const float* __restrict__ bias,
                            int outsel, int do_relu) {
    int warp = (blockIdx.x * blockDim.x + threadIdx.x) >> 5;
    if (warp >= NN) return;
    int lane = threadIdx.x & 31;
    const __half* __restrict__ xlh = g_xlh;
    __half* __restrict__ out = bufh(outsel);

    const float4 xrv  = *reinterpret_cast<const float4*>(&g_xr[(size_t)warp * HD + lane * 4]);
    const float4 attv = *reinterpret_cast<const float4*>(&att[lane * 4]);

    float m0 = -1e30f, s0 = 0.f, m1 = -1e30f, s1 = 0.f;
    float4 a0 = make_float4(0.f, 0.f, 0.f, 0.f);
    float4 a1 = make_float4(0.f, 0.f, 0.f, 0.f);

    const int beg = g_rowptr[warp];
    const int end = g_rowptr[warp + 1];

    int e = beg;
    for (; e + 1 < end; e += 2) {
        int sA = g_srcarr[e];
        int sB = g_srcarr[e + 1];
        const float4 xA = load_xl_h(xlh, sA, lane);
        const float4 xB = load_xl_h(xlh, sB, lane);

        float pA = lrelu(xA.x + xrv.x) * attv.x + lrelu(xA.y + xrv.y) * attv.y
                 + lrelu(xA.z + xrv.z) * attv.z + lrelu(xA.w + xrv.w) * attv.w;
        float pB = lrelu(xB.x + xrv.x) * attv.x + lrelu(xB.y + xrv.y) * attv.y
                 + lrelu(xB.z + xrv.z) * attv.z + lrelu(xB.w + xrv.w) * attv.w;
        pA += __shfl_xor_sync(0xffffffffu, pA, 1);
        pB += __shfl_xor_sync(0xffffffffu, pB, 1);
        pA += __shfl_xor_sync(0xffffffffu, pA, 2);
        pB += __shfl_xor_sync(0xffffffffu, pB, 2);
        pA += __shfl_xor_sync(0xffffffffu, pA, 4);
        pB += __shfl_xor_sync(0xffffffffu, pB, 4);

        osm_update(m0, s0, a0, pA, xA);
        osm_update(m1, s1, a1, pB, xB);
    }
    if (e < end) {
        int sA = g_srcarr[e];
        const float4 xA = load_xl_h(xlh, sA, lane);
        float pA = lrelu(xA.x + xrv.x) * attv.x + lrelu(xA.y + xrv.y) * attv.y
                 + lrelu(xA.z + xrv.z) * attv.z + lrelu(xA.w + xrv.w) * attv.w;
        pA += __shfl_xor_sync(0xffffffffu, pA, 1);
        pA += __shfl_xor_sync(0xffffffffu, pA, 2);
        pA += __shfl_xor_sync(0xffffffffu, pA, 4);
        osm_update(m0, s0, a0, pA, xA);
    }

    // merge the two states (exact)
    float m = fmaxf(m0, m1);
    float c0 = __expf(m0 - m);
    float c1 = (s1 > 0.f) ? __expf(m1 - m) : 0.f;
    float s = s0 * c0 + s1 * c1;
    float4 acc;
    acc.x = a0.x * c0 + a1.x * c1;
    acc.y = a0.y * c0 + a1.y * c1;
    acc.z = a0.z * c0 + a1.z * c1;
    acc.w = a0.w * c0 + a1.w * c1;

    float inv = 1.f / (s + 1e-16f);
    const float4 bv = *reinterpret_cast<const float4*>(&bias[lane * 4]);
    float4 o;
    o.x = acc.x * inv + bv.x;
    o.y = acc.y * inv + bv.y;
    o.z = acc.z * inv + bv.z;
    o.w = acc.w * inv + bv.w;
    if (do_relu) {
        o.x = fmaxf(o.x, 0.f); o.y = fmaxf(o.y, 0.f);
        o.z = fmaxf(o.z, 0.f); o.w = fmaxf(o.w, 0.f);
    }
    uint2 ov;
    ov.x = pack_h2(o.x, o.y);
    ov.y = pack_h2(o.z, o.w);
    *reinterpret_cast<uint2*>(&out[(size_t)warp * HD + lane * 4]) = ov;
}

// ---------------- pooling + classifier ----------------
__global__ void k_pool(int hsel) {
    const __half* __restrict__ h = bufh(hsel);
    int col = threadIdx.x;   // blockDim = 128
    float acc = 0.f;
    for (int r = blockIdx.x; r < NN; r += gridDim.x)
        acc += __half2float(h[(size_t)r * HD + col]);
    atomicAdd(&g_pool[col], acc);
}

__global__ void k_classify(const float* __restrict__ W, const float* __restrict__ b,
                           float* __restrict__ out) {
    int j = threadIdx.x;
    if (j < 2) {
        float s = 0.f;
        const float invn = 1.f / (float)NN;
        for (int k = 0; k < HD; k++)
            s += g_pool[k] * invn * W[k * 2 + j];
        out[j] = s + b[j];
    }
}

// ---------------- launch ----------------
extern "C" void kernel_launch(void* const* d_in, const int* in_sizes, int n_in,
                              void* d_out, int out_size) {
    const float* x  = (const float*)d_in[0];
    const int*   ei = (const int*)d_in[1];   // int32 (JAX x64 disabled)
    const float* Wl[4]  = {(const float*)d_in[2],  (const float*)d_in[6],
                           (const float*)d_in[10], (const float*)d_in[14]};
    const float* Wr[4]  = {(const float*)d_in[3],  (const float*)d_in[7],
                           (const float*)d_in[11], (const float*)d_in[15]};
    const float* att[4] = {(const float*)d_in[4],  (const float*)d_in[8],
                           (const float*)d_in[12], (const float*)d_in[16]};
    const float* bia[4] = {(const float*)d_in[5],  (const float*)d_in[9],
                           (const float*)d_in[13], (const float*)d_in[17]};
    const float* clfW = (const float*)d_in[18];
    const float* clfb = (const float*)d_in[19];
    float* out = (float*)d_out;

    cudaFuncSetAttribute(k_gemm_dual<0>, cudaFuncAttributeMaxDynamicSharedMemorySize,
                         GM_SMEM_BYTES);
    cudaFuncSetAttribute(k_gemm_dual<1>, cudaFuncAttributeMaxDynamicSharedMemorySize,
                         GM_SMEM_BYTES);

    const int TB = 256;
    const int gN  = (NN + TB - 1) / TB;
    const int gE  = (EE + TB - 1) / TB;
    const int gSc = (NN + 1023) / 1024;            // 49
    const int gGm = (NN + 63) / 64;                // 782 (M=64 dual-output tiles)
    const int gAg = (NN * 32 + TB - 1) / TB;       // warp per node

    // CSR build + weight conversion; layer-1 GEMM placed 4th (ncu capture window)
    k_init<<<gN, TB>>>();
    k_hist<<<gE, TB>>>(ei);
    k_wconv<<<294912 / TB, TB>>>(Wl[0], Wr[0], Wl[1], Wr[1], Wl[2], Wr[2], Wl[3], Wr[3]);
    k_gemm_dual<0><<<gGm, TB, GM_SMEM_BYTES>>>(x, -1, 0, NN, FIN);   // layer 1 GEMM
    k_scan_block<<<gSc, 1024>>>();
    k_scan_top<<<1, 64>>>(gSc);
    k_finalize_csr<<<gN, TB>>>();
    k_scatter<<<gE, TB>>>(ei);

    // layer 1 aggregation
    k_aggregate<<<gAg, TB>>>(att[0], bia[0], 2, 1);
    // layer 2: A = hA(2)
    k_gemm_dual<1><<<gGm, TB, GM_SMEM_BYTES>>>(nullptr, 2, 196608, NN, HD);
    k_aggregate<<<gAg, TB>>>(att[1], bia[1], 3, 1);
    // layer 3: A = hB(3)
    k_gemm_dual<1><<<gGm, TB, GM_SMEM_BYTES>>>(nullptr, 3, 229376, NN, HD);
    k_aggregate<<<gAg, TB>>>(att[2], bia[2], 2, 1);
    // layer 4 (no relu): A = hA(2)
    k_gemm_dual<1><<<gGm, TB, GM_SMEM_BYTES>>>(nullptr, 2, 262144, NN, HD);
    k_aggregate<<<gAg, TB>>>(att[3], bia[3], 3, 0);

    // mean-pool + classifier
    k_pool<<<512, 128>>>(3);
    k_classify<<<1, 32>>>(clfW, clfb, out);
}